// round 1
// baseline (speedup 1.0000x reference)
#include <cuda_runtime.h>

// Bilinear resample: B=16, S=128, C=128, fp32.
// d_in[0] = offsets [B,S,S,2], d_in[1] = inputs [B,S,S,C], out [B,S,S,C].
//
// One warp per output pixel: each lane loads one float4 (4 channels) from
// each of the 4 gathered corner rows (each row = 512B contiguous), lerps,
// and writes one float4. All gathers are fully-coalesced 512B transactions.

#define S 128
#define C 128
#define NPIX (16 * S * S)   // 262144 output pixels

__global__ __launch_bounds__(256) void resample_kernel(
    const float* __restrict__ offsets,
    const float* __restrict__ inputs,
    float* __restrict__ out)
{
    const int gtid = blockIdx.x * blockDim.x + threadIdx.x;
    const int warp = gtid >> 5;           // pixel index in [0, NPIX)
    const int lane = gtid & 31;           // float4 index within channel row
    if (warp >= NPIX) return;

    const int j = warp & (S - 1);         // col
    const int i = (warp >> 7) & (S - 1);  // row
    const int b = warp >> 14;             // batch

    // All lanes broadcast-read the same 8 bytes.
    const float2 off = __ldg(reinterpret_cast<const float2*>(offsets) + warp);

    // coords = clip(offset + grid, 0, S-1); coord0 = row, coord1 = col
    const float y = fminf(fmaxf(off.x + (float)i, 0.0f), (float)(S - 1));
    const float x = fminf(fmaxf(off.y + (float)j, 0.0f), (float)(S - 1));

    const float y0f = floorf(y);
    const float x0f = floorf(x);
    const int y0 = (int)y0f;
    const int x0 = (int)x0f;
    const int y1 = (int)ceilf(y);   // matches reference's ceil (== y0 when integral)
    const int x1 = (int)ceilf(x);
    const float fy = y - y0f;       // row fraction  (reference "fx")
    const float fx = x - x0f;       // col fraction  (reference "fy")

    const float4* base = reinterpret_cast<const float4*>(inputs)
                       + (size_t)b * (S * S * (C / 4));

    // Each spatial location is C/4 = 32 float4s; lane picks its float4.
    const int p00 = (y0 * S + x0) * (C / 4) + lane;
    const int p01 = (y0 * S + x1) * (C / 4) + lane;
    const int p10 = (y1 * S + x0) * (C / 4) + lane;
    const int p11 = (y1 * S + x1) * (C / 4) + lane;

    const float4 v00 = __ldg(base + p00);   // lt
    const float4 v01 = __ldg(base + p01);   // rt
    const float4 v10 = __ldg(base + p10);   // lb
    const float4 v11 = __ldg(base + p11);   // rb

    // vals_t = lt + (rt-lt)*fy_col ; vals_b = lb + (rb-lb)*fy_col ; out = t + (b-t)*fx_row
    float4 t, bo, o;
    t.x = v00.x + (v01.x - v00.x) * fx;
    t.y = v00.y + (v01.y - v00.y) * fx;
    t.z = v00.z + (v01.z - v00.z) * fx;
    t.w = v00.w + (v01.w - v00.w) * fx;
    bo.x = v10.x + (v11.x - v10.x) * fx;
    bo.y = v10.y + (v11.y - v10.y) * fx;
    bo.z = v10.z + (v11.z - v10.z) * fx;
    bo.w = v10.w + (v11.w - v10.w) * fx;
    o.x = t.x + (bo.x - t.x) * fy;
    o.y = t.y + (bo.y - t.y) * fy;
    o.z = t.z + (bo.z - t.z) * fy;
    o.w = t.w + (bo.w - t.w) * fy;

    reinterpret_cast<float4*>(out)[(size_t)warp * (C / 4) + lane] = o;
}

extern "C" void kernel_launch(void* const* d_in, const int* in_sizes, int n_in,
                              void* d_out, int out_size)
{
    const float* offsets = (const float*)d_in[0];
    const float* inputs  = (const float*)d_in[1];
    float* out = (float*)d_out;

    // NPIX warps, 8 warps per 256-thread block
    const int threads = 256;
    const int blocks = (NPIX * 32) / threads;   // 32768
    resample_kernel<<<blocks, threads>>>(offsets, inputs, out);
}

// round 2
// speedup vs baseline: 1.0619x; 1.0619x over previous
#include <cuda_runtime.h>

// Bilinear resample: B=16, S=128, C=128, fp32.
// One warp per TWO output pixels: 8 independent 512B gathers in flight per
// warp (doubled MLP vs R1), one float4 broadcast covers both offset pairs.

#define S 128
#define C 128
#define NPIX (16 * S * S)   // 262144 output pixels

__global__ __launch_bounds__(256) void resample_kernel(
    const float* __restrict__ offsets,
    const float* __restrict__ inputs,
    float* __restrict__ out)
{
    const int gtid = blockIdx.x * blockDim.x + threadIdx.x;
    const int warp = gtid >> 5;                // warp index -> pixel pair
    const int lane = gtid & 31;
    const int pix0 = warp * 2;                 // even pixel, same row as pix0+1
    if (pix0 >= NPIX) return;

    const int j0 = pix0 & (S - 1);             // col of pixel 0 (even)
    const int i  = (pix0 >> 7) & (S - 1);      // row (shared: j0 even => same row)
    const int b  = pix0 >> 14;                 // batch (shared)

    // One 16B broadcast load = offsets for both pixels (16B-aligned: pix0 even).
    const float4 off2 = __ldg(reinterpret_cast<const float4*>(offsets) + warp);

    // ---- pixel 0 coords ----
    const float y0c = fminf(fmaxf(off2.x + (float)i,        0.0f), (float)(S - 1));
    const float x0c = fminf(fmaxf(off2.y + (float)j0,       0.0f), (float)(S - 1));
    // ---- pixel 1 coords ----
    const float y1c = fminf(fmaxf(off2.z + (float)i,        0.0f), (float)(S - 1));
    const float x1c = fminf(fmaxf(off2.w + (float)(j0 + 1), 0.0f), (float)(S - 1));

    const float ay0f = floorf(y0c), ax0f = floorf(x0c);
    const float by0f = floorf(y1c), bx0f = floorf(x1c);
    const int aY0 = (int)ay0f, aX0 = (int)ax0f;
    const int aY1 = (int)ceilf(y0c), aX1 = (int)ceilf(x0c);
    const int bY0 = (int)by0f, bX0 = (int)bx0f;
    const int bY1 = (int)ceilf(y1c), bX1 = (int)ceilf(x1c);
    const float afy = y0c - ay0f, afx = x0c - ax0f;   // row frac, col frac (pix0)
    const float bfy = y1c - by0f, bfx = x1c - bx0f;   // (pix1)

    const float4* base = reinterpret_cast<const float4*>(inputs)
                       + (size_t)b * (S * S * (C / 4));

    // 8 independent coalesced 512B gathers, front-batched for MLP.
    const float4 a00 = __ldg(base + (aY0 * S + aX0) * (C / 4) + lane);
    const float4 a01 = __ldg(base + (aY0 * S + aX1) * (C / 4) + lane);
    const float4 a10 = __ldg(base + (aY1 * S + aX0) * (C / 4) + lane);
    const float4 a11 = __ldg(base + (aY1 * S + aX1) * (C / 4) + lane);
    const float4 b00 = __ldg(base + (bY0 * S + bX0) * (C / 4) + lane);
    const float4 b01 = __ldg(base + (bY0 * S + bX1) * (C / 4) + lane);
    const float4 b10 = __ldg(base + (bY1 * S + bX0) * (C / 4) + lane);
    const float4 b11 = __ldg(base + (bY1 * S + bX1) * (C / 4) + lane);

    // lerp: t = lt + (rt-lt)*fcol ; bo = lb + (rb-lb)*fcol ; o = t + (bo-t)*frow
    float4 o0, o1;
    {
        float4 t, bo;
        t.x  = a00.x + (a01.x - a00.x) * afx;
        t.y  = a00.y + (a01.y - a00.y) * afx;
        t.z  = a00.z + (a01.z - a00.z) * afx;
        t.w  = a00.w + (a01.w - a00.w) * afx;
        bo.x = a10.x + (a11.x - a10.x) * afx;
        bo.y = a10.y + (a11.y - a10.y) * afx;
        bo.z = a10.z + (a11.z - a10.z) * afx;
        bo.w = a10.w + (a11.w - a10.w) * afx;
        o0.x = t.x + (bo.x - t.x) * afy;
        o0.y = t.y + (bo.y - t.y) * afy;
        o0.z = t.z + (bo.z - t.z) * afy;
        o0.w = t.w + (bo.w - t.w) * afy;
    }
    {
        float4 t, bo;
        t.x  = b00.x + (b01.x - b00.x) * bfx;
        t.y  = b00.y + (b01.y - b00.y) * bfx;
        t.z  = b00.z + (b01.z - b00.z) * bfx;
        t.w  = b00.w + (b01.w - b00.w) * bfx;
        bo.x = b10.x + (b11.x - b10.x) * bfx;
        bo.y = b10.y + (b11.y - b10.y) * bfx;
        bo.z = b10.z + (b11.z - b10.z) * bfx;
        bo.w = b10.w + (b11.w - b10.w) * bfx;
        o1.x = t.x + (bo.x - t.x) * bfy;
        o1.y = t.y + (bo.y - t.y) * bfy;
        o1.z = t.z + (bo.z - t.z) * bfy;
        o1.w = t.w + (bo.w - t.w) * bfy;
    }

    float4* outp = reinterpret_cast<float4*>(out) + (size_t)pix0 * (C / 4) + lane;
    outp[0]       = o0;
    outp[C / 4]   = o1;
}

extern "C" void kernel_launch(void* const* d_in, const int* in_sizes, int n_in,
                              void* d_out, int out_size)
{
    const float* offsets = (const float*)d_in[0];
    const float* inputs  = (const float*)d_in[1];
    float* out = (float*)d_out;

    const int threads = 256;                      // 8 warps = 16 pixels / block
    const int blocks = (NPIX / 2 * 32) / threads; // 16384
    resample_kernel<<<blocks, threads>>>(offsets, inputs, out);
}